// round 11
// baseline (speedup 1.0000x reference)
#include <cuda_runtime.h>

// Per-pixel dynamic conv (KPN style), K=5. B=4, C=64, H=128, W=128.
// out[b,c,h,w] = sum_t core[b,t,c,h,w] * data_pad[b,c,h+t/5-2, w+t%5-2]
// Pure HBM stream: core = 419 MB read-once; min traffic 453 MB.
//
// R6 = champion R2 config (regs<=64, occ 4, 5 front-batched __ldcs/di-row)
//      + vectorized interior data-row loads (8 predicated LDG.32 -> 
//        2x LDG.128 + 1x LDG.64 for the 30/32 interior lanes).
// Lessons: R3/R4 (register-funded depth) neutral/worse; R5 (L2 prefetch)
// regressed. DRAM ~85% is the pattern ceiling; this round trims L1/issue only.

#define KS 5
#define PAD 2

namespace {
constexpr int B = 4, C = 64, H = 128, W = 128;
constexpr int HW = H * W;
constexpr int CHW = C * HW;
constexpr int TAPS = KS * KS;
}

__global__ __launch_bounds__(256, 4)
void dynconv_kernel(const float* __restrict__ data,
                    const float* __restrict__ core,
                    float* __restrict__ out) {
    int idx = blockIdx.x * 256 + threadIdx.x;   // over B*C*H*(W/4) = 1048576

    int w4 = idx & 31;
    int h  = (idx >> 5) & (H - 1);
    int c  = (idx >> 12) & (C - 1);
    int b  = idx >> 18;
    int w0 = w4 << 2;

    const float* dbase = data + ((long)(b * C + c)) * HW;
    const float* cbase = core + ((long)(b * TAPS) * C + c) * HW + h * W + w0;

    // interior in w: need columns w0-4 .. w0+5 all in [0, W)
    bool w_interior = (w0 >= 4) && (w0 <= W - 8);

    float4 acc = make_float4(0.f, 0.f, 0.f, 0.f);

    #pragma unroll
    for (int di = 0; di < KS; di++) {
        int hh = h + di - PAD;
        const float* cp = cbase + (long)(di * KS) * CHW;

        // ---- 5 back-to-back streaming core loads (DRAM stream) ----
        float4 c0 = __ldcs(reinterpret_cast<const float4*>(cp));
        float4 c1 = __ldcs(reinterpret_cast<const float4*>(cp + (long)CHW));
        float4 c2 = __ldcs(reinterpret_cast<const float4*>(cp + (long)CHW * 2));
        float4 c3 = __ldcs(reinterpret_cast<const float4*>(cp + (long)CHW * 3));
        float4 c4 = __ldcs(reinterpret_cast<const float4*>(cp + (long)CHW * 4));

        // ---- data row (L1/L2 hits): values data[w0-2 .. w0+5] -> row[0..7] ----
        float row[8];
        if (hh >= 0 && hh < H) {
            const float* dr = dbase + hh * W;
            if (w_interior) {
                // vector fast path: 2x float4 + 1x float2, no predicates
                float4 a = *reinterpret_cast<const float4*>(dr + w0 - 4); // w0-4..w0-1
                float4 m = *reinterpret_cast<const float4*>(dr + w0);     // w0  ..w0+3
                float2 e = *reinterpret_cast<const float2*>(dr + w0 + 4); // w0+4..w0+5
                row[0] = a.z; row[1] = a.w;
                row[2] = m.x; row[3] = m.y; row[4] = m.z; row[5] = m.w;
                row[6] = e.x; row[7] = e.y;
            } else {
                #pragma unroll
                for (int k = 0; k < 8; k++) {
                    int ww = w0 + k - PAD;
                    row[k] = (ww >= 0 && ww < W) ? __ldg(dr + ww) : 0.f;
                }
            }
        } else {
            #pragma unroll
            for (int k = 0; k < 8; k++) row[k] = 0.f;
        }

        // ---- consume: output col m of tap dj uses row[m + dj] ----
        acc.x += c0.x * row[0]; acc.y += c0.y * row[1]; acc.z += c0.z * row[2]; acc.w += c0.w * row[3];
        acc.x += c1.x * row[1]; acc.y += c1.y * row[2]; acc.z += c1.z * row[3]; acc.w += c1.w * row[4];
        acc.x += c2.x * row[2]; acc.y += c2.y * row[3]; acc.z += c2.z * row[4]; acc.w += c2.w * row[5];
        acc.x += c3.x * row[3]; acc.y += c3.y * row[4]; acc.z += c3.z * row[5]; acc.w += c3.w * row[6];
        acc.x += c4.x * row[4]; acc.y += c4.y * row[5]; acc.z += c4.z * row[6]; acc.w += c4.w * row[7];
    }

    __stcs(reinterpret_cast<float4*>(out + (long)idx * 4), acc);
}

extern "C" void kernel_launch(void* const* d_in, const int* in_sizes, int n_in,
                              void* d_out, int out_size) {
    const float* data = (const float*)d_in[0];  // [4,64,128,128]
    const float* core = (const float*)d_in[1];  // [4,1600,128,128]
    float* out = (float*)d_out;                 // [4,64,128,128]

    int total4 = B * C * H * (W / 4);           // 1048576
    dynconv_kernel<<<total4 / 256, 256>>>(data, core, out);
}

// round 12
// speedup vs baseline: 1.0690x; 1.0690x over previous
#include <cuda_runtime.h>

// Per-pixel dynamic conv (KPN style), K=5. B=4, C=64, H=128, W=128.
// out[b,c,h,w] = sum_t core[b,t,c,h,w] * data_pad[b,c,h+t/5-2, w+t%5-2]
// Pure HBM stream: core = 419 MB read-once; min traffic 453 MB.
//
// R7 = R6 body (champion: best ncu time 65.12us, DRAM 85.8%, L1 36%)
//      with 512-thread blocks: per-tap contiguous run per block 4KB -> 8KB
//      (DRAM row-buffer locality), same 32 warps/SM (regs=64, 2 blocks/SM).
// Established: DRAM ~85.5-86% / 6.8 TB/s is this pattern's ceiling; all
// MLP/occupancy/prefetch levers are exhausted (R3/R4/R5 neutral or worse).

#define KS 5
#define PAD 2

namespace {
constexpr int B = 4, C = 64, H = 128, W = 128;
constexpr int HW = H * W;
constexpr int CHW = C * HW;
constexpr int TAPS = KS * KS;
}

__global__ __launch_bounds__(512, 2)
void dynconv_kernel(const float* __restrict__ data,
                    const float* __restrict__ core,
                    float* __restrict__ out) {
    int idx = blockIdx.x * 512 + threadIdx.x;   // over B*C*H*(W/4) = 1048576

    int w4 = idx & 31;
    int h  = (idx >> 5) & (H - 1);
    int c  = (idx >> 12) & (C - 1);
    int b  = idx >> 18;
    int w0 = w4 << 2;

    const float* dbase = data + ((long)(b * C + c)) * HW;
    const float* cbase = core + ((long)(b * TAPS) * C + c) * HW + h * W + w0;

    // interior in w: need columns w0-4 .. w0+5 all in [0, W)
    bool w_interior = (w0 >= 4) && (w0 <= W - 8);

    float4 acc = make_float4(0.f, 0.f, 0.f, 0.f);

    #pragma unroll
    for (int di = 0; di < KS; di++) {
        int hh = h + di - PAD;
        const float* cp = cbase + (long)(di * KS) * CHW;

        // ---- 5 back-to-back streaming core loads (the DRAM stream) ----
        float4 c0 = __ldcs(reinterpret_cast<const float4*>(cp));
        float4 c1 = __ldcs(reinterpret_cast<const float4*>(cp + (long)CHW));
        float4 c2 = __ldcs(reinterpret_cast<const float4*>(cp + (long)CHW * 2));
        float4 c3 = __ldcs(reinterpret_cast<const float4*>(cp + (long)CHW * 3));
        float4 c4 = __ldcs(reinterpret_cast<const float4*>(cp + (long)CHW * 4));

        // ---- data row (L1/L2 hits): values data[w0-2 .. w0+5] -> row[0..7] ----
        float row[8];
        if (hh >= 0 && hh < H) {
            const float* dr = dbase + hh * W;
            if (w_interior) {
                // vector fast path: 2x float4 + 1x float2, no predicates
                float4 a = *reinterpret_cast<const float4*>(dr + w0 - 4); // w0-4..w0-1
                float4 m = *reinterpret_cast<const float4*>(dr + w0);     // w0  ..w0+3
                float2 e = *reinterpret_cast<const float2*>(dr + w0 + 4); // w0+4..w0+5
                row[0] = a.z; row[1] = a.w;
                row[2] = m.x; row[3] = m.y; row[4] = m.z; row[5] = m.w;
                row[6] = e.x; row[7] = e.y;
            } else {
                #pragma unroll
                for (int k = 0; k < 8; k++) {
                    int ww = w0 + k - PAD;
                    row[k] = (ww >= 0 && ww < W) ? __ldg(dr + ww) : 0.f;
                }
            }
        } else {
            #pragma unroll
            for (int k = 0; k < 8; k++) row[k] = 0.f;
        }

        // ---- consume: output col m of tap dj uses row[m + dj] ----
        acc.x += c0.x * row[0]; acc.y += c0.y * row[1]; acc.z += c0.z * row[2]; acc.w += c0.w * row[3];
        acc.x += c1.x * row[1]; acc.y += c1.y * row[2]; acc.z += c1.z * row[3]; acc.w += c1.w * row[4];
        acc.x += c2.x * row[2]; acc.y += c2.y * row[3]; acc.z += c2.z * row[4]; acc.w += c2.w * row[5];
        acc.x += c3.x * row[3]; acc.y += c3.y * row[4]; acc.z += c3.z * row[5]; acc.w += c3.w * row[6];
        acc.x += c4.x * row[4]; acc.y += c4.y * row[5]; acc.z += c4.z * row[6]; acc.w += c4.w * row[7];
    }

    __stcs(reinterpret_cast<float4*>(out + (long)idx * 4), acc);
}

extern "C" void kernel_launch(void* const* d_in, const int* in_sizes, int n_in,
                              void* d_out, int out_size) {
    const float* data = (const float*)d_in[0];  // [4,64,128,128]
    const float* core = (const float*)d_in[1];  // [4,1600,128,128]
    float* out = (float*)d_out;                 // [4,64,128,128]

    int total4 = B * C * H * (W / 4);           // 1048576
    dynconv_kernel<<<total4 / 512, 512>>>(data, core, out);
}